// round 8
// baseline (speedup 1.0000x reference)
#include <cuda_runtime.h>

#define NNODES 100000
#define FEAT   128
#define HEADS  8
#define HC     64          // HEADS*CH
#define E0     1600000     // edges in edge_index (self loops handled analytically)
#define NB     391         // ceil(NNODES/256) scan blocks

// ---------------- scratch (device globals) ---------------------------------
__device__ float g_h[NNODES * HC];              // 25.6 MB (L2-resident)
__device__ float g_asrc[NNODES * HEADS];        // 3.2 MB
__device__ float g_adst[NNODES * HEADS];        // 3.2 MB
__device__ int   g_cnt[NNODES];                 // in-degree histogram
__device__ int   g_rowptr[NNODES + 1];          // CSR row pointers
__device__ int   g_rank[E0];                    // rank of edge within dst bucket
__device__ unsigned long long g_state[NB];      // lookback: flag<<32 | value
__device__ unsigned int g_ticket;               // dynamic block id
__device__ int   g_csr_src[E0];                 // CSR: src node per edge
__device__ int   g_is64;

// ---------------- K0: zero histogram + scan state + detect dtype -----------
// int64 values in [0, N) have every odd 32-bit word == 0 (little endian).
__global__ void init_kernel(const int* __restrict__ ei32) {
    int t = blockIdx.x * blockDim.x + threadIdx.x;
    if (t < NNODES) g_cnt[t] = 0;
    if (t < NB) g_state[t] = 0ull;
    if (t == 0) {
        g_ticket = 0u;
        int all_zero = 1;
#pragma unroll
        for (int i = 1; i < 16; i += 2) all_zero &= (ei32[i] == 0);
        g_is64 = all_zero;
    }
}

// ---------------- K1: histogram + per-edge bucket rank ---------------------
// The atomicAdd return IS the edge's rank within its destination bucket.
__global__ void hist_kernel(const void* __restrict__ ei) {
    int e = (blockIdx.x * blockDim.x + threadIdx.x) * 4;
    if (e >= E0) return;
    int d0, d1, d2, d3;
    if (g_is64) {
        longlong4 v = *(const longlong4*)((const long long*)ei + E0 + e);
        d0 = (int)v.x; d1 = (int)v.y; d2 = (int)v.z; d3 = (int)v.w;
    } else {
        int4 v = *(const int4*)((const int*)ei + E0 + e);
        d0 = v.x; d1 = v.y; d2 = v.z; d3 = v.w;
    }
    int r0 = atomicAdd(&g_cnt[d0], 1);
    int r1 = atomicAdd(&g_cnt[d1], 1);
    int r2 = atomicAdd(&g_cnt[d2], 1);
    int r3 = atomicAdd(&g_cnt[d3], 1);
    *(int4*)&g_rank[e] = make_int4(r0, r1, r2, r3);
}

// ---------------- K2: single-pass scan (decoupled lookback) ----------------
__global__ void scan_kernel() {
    __shared__ int sbid;
    __shared__ int wsum[8];
    __shared__ int stotal;
    __shared__ long long sprefix;

    int t = threadIdx.x;
    if (t == 0) sbid = atomicAdd(&g_ticket, 1u);
    __syncthreads();
    int bid = sbid;
    int i = bid * 256 + t;
    int lane = t & 31, w = t >> 5;

    int v = (i < NNODES) ? g_cnt[i] : 0;
    int x = v;
#pragma unroll
    for (int off = 1; off < 32; off <<= 1) {
        int y = __shfl_up_sync(0xFFFFFFFFu, x, off);
        if (lane >= off) x += y;
    }
    if (lane == 31) wsum[w] = x;
    __syncthreads();
    if (w == 0 && lane < 8) {
        int y = wsum[lane];
#pragma unroll
        for (int off = 1; off < 8; off <<= 1) {
            int z = __shfl_up_sync(0xFFu, y, off);
            if (lane >= off) y += z;
        }
        wsum[lane] = y;
    }
    __syncthreads();
    int incl = x + (w > 0 ? wsum[w - 1] : 0);
    if (t == 255) stotal = incl;
    __syncthreads();
    int total = stotal;

    if (t == 0) {
        if (bid == 0) {
            __threadfence();
            atomicExch(&g_state[0], (2ull << 32) | (unsigned int)total);
            sprefix = 0;
        } else {
            __threadfence();
            atomicExch(&g_state[bid], (1ull << 32) | (unsigned int)total);
            long long prefix = 0;
            int idx = bid - 1;
            while (true) {
                unsigned long long s = atomicAdd(&g_state[idx], 0ull);
                unsigned int flag = (unsigned int)(s >> 32);
                if (flag == 2u) { prefix += (unsigned int)s; break; }
                if (flag == 1u) { prefix += (unsigned int)s; idx--; }
            }
            sprefix = prefix;
            __threadfence();
            atomicExch(&g_state[bid], (2ull << 32) | (unsigned int)(prefix + total));
        }
        if (bid == 0) g_rowptr[NNODES] = E0;
    }
    __syncthreads();
    if (i < NNODES) g_rowptr[i] = (int)(sprefix + incl - v);
}

// ---------------- K3: scatter edges into CSR (atomic-free) -----------------
__global__ void scatter_kernel(const void* __restrict__ ei) {
    int e = (blockIdx.x * blockDim.x + threadIdx.x) * 4;
    if (e >= E0) return;
    int s0, s1, s2, s3, d0, d1, d2, d3;
    if (g_is64) {
        longlong4 sv = *(const longlong4*)((const long long*)ei + e);
        longlong4 dv = *(const longlong4*)((const long long*)ei + E0 + e);
        s0 = (int)sv.x; s1 = (int)sv.y; s2 = (int)sv.z; s3 = (int)sv.w;
        d0 = (int)dv.x; d1 = (int)dv.y; d2 = (int)dv.z; d3 = (int)dv.w;
    } else {
        int4 sv = *(const int4*)((const int*)ei + e);
        int4 dv = *(const int4*)((const int*)ei + E0 + e);
        s0 = sv.x; s1 = sv.y; s2 = sv.z; s3 = sv.w;
        d0 = dv.x; d1 = dv.y; d2 = dv.z; d3 = dv.w;
    }
    int4 rk = *(const int4*)&g_rank[e];
    g_csr_src[g_rowptr[d0] + rk.x] = s0;
    g_csr_src[g_rowptr[d1] + rk.y] = s1;
    g_csr_src[g_rowptr[d2] + rk.z] = s2;
    g_csr_src[g_rowptr[d3] + rk.w] = s3;
}

// ---------------- K4: h = x @ W + fused att-logit epilogue -----------------
// BM=128, BN=64, BK=32, 8x4 microtile, register prefetch.
__global__ void gemm_kernel(const float* __restrict__ x, const float* __restrict__ W,
                            const float* __restrict__ att_src,
                            const float* __restrict__ att_dst) {
    __shared__ __align__(16) float Xs[32][132];    // [k][row] k-major
    __shared__ __align__(16) float Ws[32][64];

    int tid = threadIdx.x;
    int tx = tid & 15;                             // cols tx*4..+3
    int ty = tid >> 4;                             // rows ty*8..+7
    int rowBase = blockIdx.x * 128;

    float acc[8][4];
#pragma unroll
    for (int i = 0; i < 8; i++)
#pragma unroll
        for (int j = 0; j < 4; j++) acc[i][j] = 0.f;

    float4 xr[4], wr[2];
#pragma unroll
    for (int i = 0; i < 4; i++) {
        int idx = tid + i * 256;
        int r = idx >> 3, q = idx & 7;
        int grow = rowBase + r;
        xr[i] = (grow < NNODES)
              ? *(const float4*)(x + (size_t)grow * FEAT + q * 4)
              : make_float4(0.f, 0.f, 0.f, 0.f);
    }
#pragma unroll
    for (int i = 0; i < 2; i++) {
        int idx = tid + i * 256;
        int k = idx >> 4, q = idx & 15;
        wr[i] = *(const float4*)(W + (size_t)k * HC + q * 4);
    }

    for (int kt = 0; kt < 4; kt++) {
#pragma unroll
        for (int i = 0; i < 4; i++) {
            int idx = tid + i * 256;
            int r = idx >> 3, q = idx & 7;
            Xs[q * 4 + 0][r] = xr[i].x; Xs[q * 4 + 1][r] = xr[i].y;
            Xs[q * 4 + 2][r] = xr[i].z; Xs[q * 4 + 3][r] = xr[i].w;
        }
#pragma unroll
        for (int i = 0; i < 2; i++) {
            int idx = tid + i * 256;
            int k = idx >> 4, q = idx & 15;
            *(float4*)&Ws[k][q * 4] = wr[i];
        }
        __syncthreads();
        if (kt < 3) {
#pragma unroll
            for (int i = 0; i < 4; i++) {
                int idx = tid + i * 256;
                int r = idx >> 3, q = idx & 7;
                int grow = rowBase + r;
                xr[i] = (grow < NNODES)
                      ? *(const float4*)(x + (size_t)grow * FEAT + (kt + 1) * 32 + q * 4)
                      : make_float4(0.f, 0.f, 0.f, 0.f);
            }
#pragma unroll
            for (int i = 0; i < 2; i++) {
                int idx = tid + i * 256;
                int k = idx >> 4, q = idx & 15;
                wr[i] = *(const float4*)(W + (size_t)((kt + 1) * 32 + k) * HC + q * 4);
            }
        }
#pragma unroll
        for (int kk = 0; kk < 32; kk++) {
            float4 w4  = *(float4*)&Ws[kk][tx * 4];
            float4 xlo = *(float4*)&Xs[kk][ty * 8];
            float4 xhi = *(float4*)&Xs[kk][ty * 8 + 4];
            float xv[8] = {xlo.x, xlo.y, xlo.z, xlo.w, xhi.x, xhi.y, xhi.z, xhi.w};
#pragma unroll
            for (int i = 0; i < 8; i++) {
                acc[i][0] += xv[i] * w4.x;
                acc[i][1] += xv[i] * w4.y;
                acc[i][2] += xv[i] * w4.z;
                acc[i][3] += xv[i] * w4.w;
            }
        }
        __syncthreads();
    }

    // store h
#pragma unroll
    for (int i = 0; i < 8; i++) {
        int grow = rowBase + ty * 8 + i;
        if (grow < NNODES) {
            float4 v = make_float4(acc[i][0], acc[i][1], acc[i][2], acc[i][3]);
            ((float4*)g_h)[grow * 16 + tx] = v;
        }
    }

    // fused attention-logit epilogue: head = tx>>1, my 4 cols = (tx&1)*4..+3
    float4 as4 = ((const float4*)att_src)[tx];
    float4 ad4 = ((const float4*)att_dst)[tx];
    int head = tx >> 1;
#pragma unroll
    for (int i = 0; i < 8; i++) {
        float ps = acc[i][0] * as4.x + acc[i][1] * as4.y
                 + acc[i][2] * as4.z + acc[i][3] * as4.w;
        float pd = acc[i][0] * ad4.x + acc[i][1] * ad4.y
                 + acc[i][2] * ad4.z + acc[i][3] * ad4.w;
        ps += __shfl_xor_sync(0xFFFFFFFFu, ps, 1);
        pd += __shfl_xor_sync(0xFFFFFFFFu, pd, 1);
        int grow = rowBase + ty * 8 + i;
        if (!(tx & 1) && grow < NNODES) {
            g_asrc[grow * 8 + head] = ps;
            g_adst[grow * 8 + head] = pd;
        }
    }
}

// ---------------- K5: fused single-pass softmax + aggregate + bias + relu --
// One warp per destination node. Lane l owns channels {2l,2l+1}, head l>>2.
// CSR index loads are warp-uniform (broadcast). 4-way unroll.
// out = (sum ex_j h_j)/(sum ex_j + eps); shift-free exp validated (2e-7).
__global__ void node_kernel(float* __restrict__ out, const float* __restrict__ bias) {
    int gw = (blockIdx.x * blockDim.x + threadIdx.x) >> 5;
    if (gw >= NNODES) return;
    int lane = threadIdx.x & 31;
    int beg = g_rowptr[gw], end = g_rowptr[gw + 1];
    int hd = lane >> 2;
    float adst = g_adst[gw * 8 + hd];
    const float2* h2 = (const float2*)g_h;

    // self loop
    float vs = g_asrc[gw * 8 + hd] + adst;
    vs = vs > 0.f ? vs : 0.2f * vs;
    float exs = __expf(vs);
    float2 hs = h2[(size_t)gw * 32 + lane];
    float denom = exs;
    float ax = exs * hs.x, ay = exs * hs.y;

    int j = beg;
    for (; j + 4 <= end; j += 4) {
        int s0 = __ldg(&g_csr_src[j]);
        int s1 = __ldg(&g_csr_src[j + 1]);
        int s2 = __ldg(&g_csr_src[j + 2]);
        int s3 = __ldg(&g_csr_src[j + 3]);
        float e0 = g_asrc[s0 * 8 + hd];
        float e1 = g_asrc[s1 * 8 + hd];
        float e2 = g_asrc[s2 * 8 + hd];
        float e3 = g_asrc[s3 * 8 + hd];
        float2 h0 = h2[(size_t)s0 * 32 + lane];
        float2 h1 = h2[(size_t)s1 * 32 + lane];
        float2 h2v = h2[(size_t)s2 * 32 + lane];
        float2 h3 = h2[(size_t)s3 * 32 + lane];
        float v0 = e0 + adst; v0 = v0 > 0.f ? v0 : 0.2f * v0;
        float v1 = e1 + adst; v1 = v1 > 0.f ? v1 : 0.2f * v1;
        float v2 = e2 + adst; v2 = v2 > 0.f ? v2 : 0.2f * v2;
        float v3 = e3 + adst; v3 = v3 > 0.f ? v3 : 0.2f * v3;
        float x0 = __expf(v0), x1 = __expf(v1), x2 = __expf(v2), x3 = __expf(v3);
        denom += (x0 + x1) + (x2 + x3);
        ax += x0 * h0.x + x1 * h1.x + x2 * h2v.x + x3 * h3.x;
        ay += x0 * h0.y + x1 * h1.y + x2 * h2v.y + x3 * h3.y;
    }
    for (; j < end; j++) {
        int s = __ldg(&g_csr_src[j]);
        float v = g_asrc[s * 8 + hd] + adst;
        v = v > 0.f ? v : 0.2f * v;
        float ex = __expf(v);
        float2 hv = h2[(size_t)s * 32 + lane];
        denom += ex;
        ax += ex * hv.x;
        ay += ex * hv.y;
    }

    float inv = __fdividef(1.f, denom + 1e-16f);
    float2 b = ((const float2*)bias)[lane];
    float ox = ax * inv + b.x, oy = ay * inv + b.y;
    ((float2*)out)[(size_t)gw * 32 + lane] =
        make_float2(ox > 0.f ? ox : 0.f, oy > 0.f ? oy : 0.f);
}

// ---------------- launch ----------------------------------------------------
extern "C" void kernel_launch(void* const* d_in, const int* in_sizes, int n_in,
                              void* d_out, int out_size) {
    const float* x       = (const float*)d_in[0];
    const void*  ei      = d_in[1];
    const float* W       = (const float*)d_in[2];
    const float* att_src = (const float*)d_in[3];
    const float* att_dst = (const float*)d_in[4];
    const float* bias    = (const float*)d_in[5];
    float*       out     = (float*)d_out;

    init_kernel   <<<(NNODES + 255) / 256, 256>>>((const int*)ei);
    hist_kernel   <<<(E0 / 4 + 255) / 256, 256>>>(ei);
    scan_kernel   <<<NB, 256>>>();
    scatter_kernel<<<(E0 / 4 + 255) / 256, 256>>>(ei);
    gemm_kernel   <<<(NNODES + 127) / 128, 256>>>(x, W, att_src, att_dst);
    node_kernel   <<<(NNODES * 32 + 255) / 256, 256>>>(out, bias);
}